// round 1
// baseline (speedup 1.0000x reference)
#include <cuda_runtime.h>
#include <math.h>

#define N_TOK    65536
#define CDIM     256
#define KNUM     1024
#define HW       4096
#define TM       32
#define NTHREADS 512
#define LPAD     1040          // logits row pad (floats): 16B aligned, breaks 32-bank stride
#define ZPAD     36            // zT row pad (floats)
#define CHW      (CDIM*HW)
#define Q_ELEMS  16777216
#define IDX_OFF  Q_ELEMS
#define SCAL_OFF (Q_ELEMS + N_TOK)

#define SMEM_FLOATS (TM*LPAD + CDIM*ZPAD + 8*KNUM + 128)
#define SMEM_BYTES  (SMEM_FLOATS * 4)

// ---------------- device scratch (static; no allocations) ----------------
__device__ float g_cbT[CDIM * KNUM];   // codebook transposed: [c][k]
__device__ float g_avgp[KNUM];         // sum over rows of p_k (temp 0.01)
__device__ int   g_hist[KNUM];         // argmax histogram
__device__ float g_ent;                // sum over rows of (T/S - log S)
__device__ float g_sse;                // sum (z - q)^2

// FFMA-only exp: MUFU is only 0.5 op/cyc/SM on this part; 67M exps would cost
// ~470us via expf. Range-reduced 2^f Taylor, rel err ~1e-8 on [-87, 0].
__device__ __forceinline__ float fast_exp(float x) {
    x = fmaxf(x, -87.0f);
    float t = x * 1.4426950408889634f;          // x * log2(e)
    float k = t + 12582912.0f;                  // round-to-nearest via magic
    int   n = __float_as_int(k) - __float_as_int(12582912.0f);
    float f = t - (k - 12582912.0f);            // f in [-0.5, 0.5]
    const float c1 = 0.6931471805599453f, c2 = 0.2402265069591007f,
                c3 = 0.05550410866482158f, c4 = 0.009618129107628477f,
                c5 = 0.001333355814642844f, c6 = 1.5403530393381609e-4f,
                c7 = 1.5252733804059840e-5f;
    float p = c7;
    p = fmaf(p, f, c6); p = fmaf(p, f, c5); p = fmaf(p, f, c4);
    p = fmaf(p, f, c3); p = fmaf(p, f, c2); p = fmaf(p, f, c1);
    p = fmaf(p, f, 1.0f);
    return p * __int_as_float((n + 127) << 23);
}

// ---------------- prep: transpose codebook, zero accumulators ----------------
__global__ void prep_kernel(const float* __restrict__ cb) {
    int j = blockIdx.x;        // codebook entry 0..1023
    int c = threadIdx.x;       // dim 0..255
    g_cbT[c * KNUM + j] = cb[j * CDIM + c];
    if (j == 0) {
        for (int k = c; k < KNUM; k += CDIM) { g_avgp[k] = 0.0f; g_hist[k] = 0; }
        if (c == 0) { g_ent = 0.0f; g_sse = 0.0f; }
    }
}

// ---------------- main fused kernel ----------------
__global__ __launch_bounds__(NTHREADS, 1)
void main_kernel(const float* __restrict__ z, const float* __restrict__ cb,
                 float* __restrict__ out) {
    extern __shared__ float smem[];
    float* s_logits = smem;                       // 32 x LPAD  (later reused as q tile)
    float* s_zT     = s_logits + TM * LPAD;       // 256 x ZPAD (zT[c][r])
    float* s_cbs    = s_zT + CDIM * ZPAD;         // 8 x 1024
    float* s_invS   = s_cbs + 8 * KNUM;           // 32
    float* s_ent    = s_invS + 32;                // 32
    int*   s_idx    = (int*)(s_ent + 32);         // 32
    float* s_red    = (float*)(s_idx + 32);       // 32

    const int tid  = threadIdx.x;
    const int n0   = blockIdx.x * TM;
    const int b    = n0 >> 12;           // n0 / 4096
    const int hw0  = n0 & (HW - 1);
    const float* zb = z + (size_t)b * CHW + hw0;

    // --- load z tile transposed: s_zT[c][r] = z[b][c][hw0+r] ---
    {
        int c = tid >> 1;
        int rbase = (tid & 1) * 16;
        const float4* src = (const float4*)(zb + (size_t)c * HW + rbase);
        #pragma unroll
        for (int j = 0; j < 4; j++) {
            float4 v = src[j];
            *(float4*)&s_zT[c * ZPAD + rbase + 4 * j] = v;
        }
    }

    // --- GEMM: logits[32][1024] = zT^T * cbT, 8x8 register tiles ---
    const int cg = tid & 127, rg = tid >> 7;
    const int c0 = cg * 8, r0 = rg * 8;
    float acc[8][8];
    #pragma unroll
    for (int i = 0; i < 8; i++)
        #pragma unroll
        for (int j = 0; j < 8; j++) acc[i][j] = 0.0f;

    for (int kc = 0; kc < CDIM / 8; kc++) {
        __syncthreads();
        // stage codebook chunk [8][1024]
        const float4* srcc = (const float4*)g_cbT + (size_t)kc * 2048;
        float4* dstc = (float4*)s_cbs;
        #pragma unroll
        for (int j = 0; j < 4; j++) {
            int i4 = tid + j * NTHREADS;
            dstc[i4] = srcc[i4];
        }
        __syncthreads();
        #pragma unroll
        for (int kk = 0; kk < 8; kk++) {
            int k = kc * 8 + kk;
            float4 a0 = *(const float4*)&s_zT[k * ZPAD + r0];
            float4 a1 = *(const float4*)&s_zT[k * ZPAD + r0 + 4];
            float4 b0 = *(const float4*)&s_cbs[kk * KNUM + c0];
            float4 b1 = *(const float4*)&s_cbs[kk * KNUM + c0 + 4];
            float az[8] = {a0.x, a0.y, a0.z, a0.w, a1.x, a1.y, a1.z, a1.w};
            float bz[8] = {b0.x, b0.y, b0.z, b0.w, b1.x, b1.y, b1.z, b1.w};
            #pragma unroll
            for (int i = 0; i < 8; i++)
                #pragma unroll
                for (int j = 0; j < 8; j++)
                    acc[i][j] = fmaf(az[i], bz[j], acc[i][j]);
        }
    }
    // write logits tile to smem
    #pragma unroll
    for (int i = 0; i < 8; i++) {
        *(float4*)&s_logits[(r0 + i) * LPAD + c0]     = make_float4(acc[i][0], acc[i][1], acc[i][2], acc[i][3]);
        *(float4*)&s_logits[(r0 + i) * LPAD + c0 + 4] = make_float4(acc[i][4], acc[i][5], acc[i][6], acc[i][7]);
    }
    __syncthreads();

    // --- per-row stats: argmax, softmax(temp=0.01) sums, entropy ---
    const int w = tid >> 5, lane = tid & 31;
    #pragma unroll
    for (int rr = 0; rr < 2; rr++) {
        int r = w * 2 + rr;
        float* Lrow = s_logits + r * LPAD;
        float bv = -1e30f; int bi = 0;
        #pragma unroll 4
        for (int i = 0; i < 32; i++) {
            int k = lane + i * 32;
            float v = Lrow[k];
            if (v > bv) { bv = v; bi = k; }
        }
        #pragma unroll
        for (int o = 16; o > 0; o >>= 1) {
            float ov = __shfl_xor_sync(0xFFFFFFFFu, bv, o);
            int   oi = __shfl_xor_sync(0xFFFFFFFFu, bi, o);
            if (ov > bv || (ov == bv && oi < bi)) { bv = ov; bi = oi; }
        }
        float m = bv;
        float S = 0.0f, T = 0.0f;
        #pragma unroll 4
        for (int i = 0; i < 32; i++) {
            int k = lane + i * 32;
            float a = (Lrow[k] - m) * 100.0f;   // /ENTROPY_TEMP
            float e = fast_exp(a);
            S += e;
            T = fmaf(a, e, T);
            Lrow[k] = e;                        // overwrite logits with unnorm probs
        }
        #pragma unroll
        for (int o = 16; o > 0; o >>= 1) {
            S += __shfl_xor_sync(0xFFFFFFFFu, S, o);
            T += __shfl_xor_sync(0xFFFFFFFFu, T, o);
        }
        if (lane == 0) {
            s_invS[r] = 1.0f / S;
            s_ent[r]  = T / S - logf(S);        // = sum_k p log p for this row
            s_idx[r]  = bi;
        }
    }
    __syncthreads();

    // --- column sums of probs -> global avg_probs accumulator ---
    #pragma unroll
    for (int h = 0; h < 2; h++) {
        int k = tid + h * NTHREADS;
        float s = 0.0f;
        #pragma unroll 8
        for (int r = 0; r < TM; r++)
            s = fmaf(s_logits[r * LPAD + k], s_invS[r], s);
        atomicAdd(&g_avgp[k], s);
    }
    if (tid < TM) {
        atomicAdd(&g_hist[s_idx[tid]], 1);
        out[IDX_OFF + n0 + tid] = (float)s_idx[tid];
    }
    if (tid == 0) {
        float s = 0.0f;
        for (int r = 0; r < TM; r++) s += s_ent[r];
        atomicAdd(&g_ent, s);
    }
    __syncthreads();   // logits smem now free -> reuse as q tile

    // --- gather codebook[idx] into smem (coalesced reads) ---
    float* s_q = s_logits;   // [32][257]
    {
        int r = tid >> 4;
        int cbase = (tid & 15) * 16;
        const float* crow = cb + (size_t)s_idx[r] * CDIM + cbase;
        #pragma unroll
        for (int j = 0; j < 4; j++) {
            float4 v = *(const float4*)(crow + 4 * j);
            s_q[r * 257 + cbase + 4 * j + 0] = v.x;
            s_q[r * 257 + cbase + 4 * j + 1] = v.y;
            s_q[r * 257 + cbase + 4 * j + 2] = v.z;
            s_q[r * 257 + cbase + 4 * j + 3] = v.w;
        }
    }
    __syncthreads();

    // --- write quantized output (coalesced) + commit-loss partial ---
    float lsse = 0.0f;
    float* outq = out + (size_t)b * CHW + hw0;
    #pragma unroll
    for (int cc = 0; cc < 16; cc++) {
        int c = cc * 16 + w;
        float q  = s_q[lane * 257 + c];
        float zv = s_zT[c * ZPAD + lane];
        float d  = zv - q;
        lsse = fmaf(d, d, lsse);
        outq[(size_t)c * HW + lane] = q;
    }
    #pragma unroll
    for (int o = 16; o > 0; o >>= 1) lsse += __shfl_xor_sync(0xFFFFFFFFu, lsse, o);
    if (lane == 0) s_red[w] = lsse;
    __syncthreads();
    if (tid == 0) {
        float s = 0.0f;
        for (int i = 0; i < 16; i++) s += s_red[i];
        atomicAdd(&g_sse, s);
    }
}

// ---------------- finalize: scalars ----------------
__global__ void final_kernel(float* __restrict__ out) {
    __shared__ float r1[32], r2[32];
    int tid = threadIdx.x;
    const float invN = 1.0f / (float)N_TOK;
    float ap = g_avgp[tid] * invN;
    float s1 = ap * logf(ap + 1e-5f);
    float pu = (float)g_hist[tid] * invN;
    float s2 = pu * logf(fmaxf(pu, 1e-10f));
    #pragma unroll
    for (int o = 16; o > 0; o >>= 1) {
        s1 += __shfl_xor_sync(0xFFFFFFFFu, s1, o);
        s2 += __shfl_xor_sync(0xFFFFFFFFu, s2, o);
    }
    if ((tid & 31) == 0) { r1[tid >> 5] = s1; r2[tid >> 5] = s2; }
    __syncthreads();
    if (tid == 0) {
        float a = 0.0f, h = 0.0f;
        for (int i = 0; i < 32; i++) { a += r1[i]; h += r2[i]; }
        float avg_entropy    = -a;
        float sample_entropy = -g_ent * invN;
        float loss_entropy   = sample_entropy - avg_entropy;
        float perplexity     = expf(-h);
        float lc             = g_sse * (1.0f / (float)Q_ELEMS);
        out[SCAL_OFF + 0] = perplexity;
        out[SCAL_OFF + 1] = 2.0f * lc;   // loss_vq
        out[SCAL_OFF + 2] = lc;          // loss_commit
        out[SCAL_OFF + 3] = loss_entropy;
    }
}

extern "C" void kernel_launch(void* const* d_in, const int* in_sizes, int n_in,
                              void* d_out, int out_size) {
    const float* z  = (const float*)d_in[0];
    const float* cb = (const float*)d_in[1];
    float* out = (float*)d_out;
    (void)in_sizes; (void)n_in; (void)out_size;

    cudaFuncSetAttribute(main_kernel, cudaFuncAttributeMaxDynamicSharedMemorySize, SMEM_BYTES);

    prep_kernel<<<KNUM, CDIM>>>(cb);
    main_kernel<<<N_TOK / TM, NTHREADS, SMEM_BYTES>>>(z, cb, out);
    final_kernel<<<1, KNUM>>>(out);
}